// round 3
// baseline (speedup 1.0000x reference)
#include <cuda_runtime.h>
#include <cfloat>

// PromptVQ: x[N,768] f32, codebook[K,768] f32 -> quantized[N,768] f32 + indices[N] tail.
// Phase 1: fp32x2 SIMT GEMM computes approx dists, winner + top-2 gap; flags near-ties.
// Phase 2: flagged tokens rescored with fp64 dots + reference fp32 rounding cascade
//          ( dist = fl( fl(x2+c2) - 2*dot ) ), argmin with first-index tie-break.

#define DIMD 768
#define TM   128
#define TKC  128
#define TD   16
#define RS_THRESH 0.015f
#define MAXFLAG 8192

__device__ float  g_c2[8192];
__device__ double g_c2d[8192];
__device__ float  g_x2[65536];
__device__ int    g_nflag;
__device__ int    g_flags[MAXFLAG];

static __device__ __forceinline__ unsigned long long pk2(float a, float b) {
    unsigned long long r;
    asm("mov.b64 %0, {%1, %2};" : "=l"(r) : "f"(a), "f"(b));
    return r;
}
static __device__ __forceinline__ void upk2(unsigned long long v, float& a, float& b) {
    asm("mov.b64 {%0, %1}, %2;" : "=f"(a), "=f"(b) : "l"(v));
}
static __device__ __forceinline__ unsigned long long ffma2(unsigned long long a,
                                                           unsigned long long b,
                                                           unsigned long long c) {
    unsigned long long d;
    asm("fma.rn.f32x2 %0, %1, %2, %3;" : "=l"(d) : "l"(a), "l"(b), "l"(c));
    return d;
}

__global__ void sqnorm_kernel(const float* __restrict__ src, float* __restrict__ dst, int rows) {
    int gwarp = (blockIdx.x * blockDim.x + threadIdx.x) >> 5;
    int lane  = threadIdx.x & 31;
    int nw    = (gridDim.x * blockDim.x) >> 5;
    for (int row = gwarp; row < rows; row += nw) {
        const float* p = src + (size_t)row * DIMD;
        float s = 0.f;
        for (int c = lane; c < DIMD; c += 32) { float v = p[c]; s = fmaf(v, v, s); }
        #pragma unroll
        for (int o = 16; o > 0; o >>= 1) s += __shfl_xor_sync(0xffffffffu, s, o);
        if (lane == 0) dst[row] = s;
    }
}

// codebook norms in fp64 (also emits f32 copy for phase 1)
__global__ void c2d_kernel(const float* __restrict__ cb, int K) {
    int gwarp = (blockIdx.x * blockDim.x + threadIdx.x) >> 5;
    int lane  = threadIdx.x & 31;
    int nw    = (gridDim.x * blockDim.x) >> 5;
    for (int row = gwarp; row < K; row += nw) {
        const float* p = cb + (size_t)row * DIMD;
        double s = 0.0;
        for (int c = lane; c < DIMD; c += 32) { double v = p[c]; s = fma(v, v, s); }
        #pragma unroll
        for (int o = 16; o > 0; o >>= 1) s += __shfl_xor_sync(0xffffffffu, s, o);
        if (lane == 0) { g_c2d[row] = s; g_c2[row] = (float)s; }
    }
}

__global__ __launch_bounds__(256, 2)
void vq_kernel(const float* __restrict__ x, const float* __restrict__ cb,
               float* __restrict__ out, int N, int K, long long out_size) {
    __shared__ float xs2[TD][2 * TM];
    __shared__ float cs[TD][TKC];
    __shared__ int   sIdx[TM];

    const int tid = threadIdx.x;
    const int tx  = tid & 15;
    const int ty  = tid >> 4;
    const int m0  = blockIdx.x * TM;

    float bestd[8], best2[8];
    int   besti[8];
    float x2r[8];
    #pragma unroll
    for (int i = 0; i < 8; i++) {
        bestd[i] = FLT_MAX; best2[i] = FLT_MAX; besti[i] = 0;
        x2r[i] = g_x2[m0 + ty * 8 + i];
    }

    const int NKT = K / TKC;
    const int NDT = DIMD / TD;

    for (int kt = 0; kt < NKT; kt++) {
        const int k0 = kt * TKC;
        unsigned long long acc[8][4];
        #pragma unroll
        for (int i = 0; i < 8; i++)
            #pragma unroll
            for (int j = 0; j < 4; j++) acc[i][j] = 0ull;

        float4 xf[2], cf[2];
        #pragma unroll
        for (int q = 0; q < 2; q++) {
            int idx = q * 256 + tid; int r = idx >> 2; int c = (idx & 3) * 4;
            xf[q] = *(const float4*)(x  + (size_t)(m0 + r) * DIMD + c);
            cf[q] = *(const float4*)(cb + (size_t)(k0 + r) * DIMD + c);
        }

        for (int dt = 0; dt < NDT; dt++) {
            __syncthreads();
            #pragma unroll
            for (int q = 0; q < 2; q++) {
                int idx = q * 256 + tid; int r = idx >> 2; int c = (idx & 3) * 4;
                ((unsigned long long*)xs2[c + 0])[r] = pk2(xf[q].x, xf[q].x);
                ((unsigned long long*)xs2[c + 1])[r] = pk2(xf[q].y, xf[q].y);
                ((unsigned long long*)xs2[c + 2])[r] = pk2(xf[q].z, xf[q].z);
                ((unsigned long long*)xs2[c + 3])[r] = pk2(xf[q].w, xf[q].w);
                cs[c + 0][r] = cf[q].x;
                cs[c + 1][r] = cf[q].y;
                cs[c + 2][r] = cf[q].z;
                cs[c + 3][r] = cf[q].w;
            }
            __syncthreads();
            if (dt + 1 < NDT) {
                #pragma unroll
                for (int q = 0; q < 2; q++) {
                    int idx = q * 256 + tid; int r = idx >> 2; int c = (idx & 3) * 4;
                    xf[q] = *(const float4*)(x  + (size_t)(m0 + r) * DIMD + (dt + 1) * TD + c);
                    cf[q] = *(const float4*)(cb + (size_t)(k0 + r) * DIMD + (dt + 1) * TD + c);
                }
            }
            #pragma unroll
            for (int d = 0; d < TD; d++) {
                const unsigned long long* xr = (const unsigned long long*)xs2[d];
                const unsigned long long* cr = (const unsigned long long*)cs[d];
                ulonglong2 a0 = *(const ulonglong2*)(xr + ty * 8);
                ulonglong2 a1 = *(const ulonglong2*)(xr + ty * 8 + 2);
                ulonglong2 a2 = *(const ulonglong2*)(xr + ty * 8 + 4);
                ulonglong2 a3 = *(const ulonglong2*)(xr + ty * 8 + 6);
                ulonglong2 b0 = *(const ulonglong2*)(cr + tx * 4);
                ulonglong2 b1 = *(const ulonglong2*)(cr + tx * 4 + 2);
                unsigned long long A[8] = {a0.x, a0.y, a1.x, a1.y, a2.x, a2.y, a3.x, a3.y};
                unsigned long long B[4] = {b0.x, b0.y, b1.x, b1.y};
                #pragma unroll
                for (int i = 0; i < 8; i++)
                    #pragma unroll
                    for (int j = 0; j < 4; j++)
                        acc[i][j] = ffma2(A[i], B[j], acc[i][j]);
            }
        }

        #pragma unroll
        for (int j = 0; j < 4; j++) {
            int k = k0 + tx * 8 + 2 * j;
            float c2a = g_c2[k];
            float c2b = g_c2[k + 1];
            #pragma unroll
            for (int i = 0; i < 8; i++) {
                float lo, hi;
                upk2(acc[i][j], lo, hi);
                float sa = x2r[i] + c2a;
                float sb = x2r[i] + c2b;
                float d0 = fmaf(-2.f, lo, sa);
                float d1 = fmaf(-2.f, hi, sb);
                if (d0 < bestd[i]) { best2[i] = bestd[i]; bestd[i] = d0; besti[i] = k; }
                else if (d0 < best2[i]) best2[i] = d0;
                if (d1 < bestd[i]) { best2[i] = bestd[i]; bestd[i] = d1; besti[i] = k + 1; }
                else if (d1 < best2[i]) best2[i] = d1;
            }
        }
    }

    // reduce top-2 across the 16 tx-lanes sharing the same 8 tokens
    #pragma unroll
    for (int i = 0; i < 8; i++) {
        float v = bestd[i], v2 = best2[i];
        int  id = besti[i];
        #pragma unroll
        for (int off = 8; off > 0; off >>= 1) {
            float ov  = __shfl_xor_sync(0xffffffffu, v,  off, 16);
            float ov2 = __shfl_xor_sync(0xffffffffu, v2, off, 16);
            int   oi  = __shfl_xor_sync(0xffffffffu, id, off, 16);
            if (ov < v || (ov == v && oi < id)) {
                v2 = fminf(v, ov2); v = ov; id = oi;
            } else {
                v2 = fminf(v2, ov);
            }
        }
        if (tx == 0) {
            sIdx[ty * 8 + i] = id;
            if (v2 - v < RS_THRESH) {       // near-tie: defer to exact rescore
                int slot = atomicAdd(&g_nflag, 1);
                if (slot < MAXFLAG) g_flags[slot] = m0 + ty * 8 + i;
            }
        }
    }
    __syncthreads();

    const long long ND = (long long)N * DIMD;
    const int warp = tid >> 5, lane = tid & 31;
    for (int r = warp; r < TM; r += 8) {
        int code = sIdx[r];
        const float4* cp = (const float4*)(cb + (size_t)code * DIMD);
        const float4* xp = (const float4*)(x + (size_t)(m0 + r) * DIMD);
        float4* op = (float4*)(out + (size_t)(m0 + r) * DIMD);
        for (int c = lane; c < DIMD / 4; c += 32) {
            float4 q = cp[c];
            float4 xv = xp[c];
            float4 o;
            o.x = xv.x + (q.x - xv.x);
            o.y = xv.y + (q.y - xv.y);
            o.z = xv.z + (q.z - xv.z);
            o.w = xv.w + (q.w - xv.w);
            op[c] = o;
        }
    }
    if (out_size >= ND + N && tid < TM) {
        out[ND + m0 + tid] = (float)sIdx[tid];
    }
}

// Exact rescore of flagged tokens: fp64 dots, then the reference's fp32 rounding
// cascade, argmin with first-index tie-break (reproduces jnp ulp-level tie behavior).
__global__ __launch_bounds__(256)
void rescore_kernel(const float* __restrict__ x, const float* __restrict__ cb,
                    float* __restrict__ out, int N, int K, long long out_size) {
    __shared__ float  xs[DIMD];
    __shared__ double red[256];
    __shared__ float  rb[256];
    __shared__ int    ri[256];

    const int tid = threadIdx.x;
    int nf = g_nflag; if (nf > MAXFLAG) nf = MAXFLAG;

    for (int f = blockIdx.x; f < nf; f += gridDim.x) {
        int n = g_flags[f];
        for (int c = tid; c < DIMD; c += 256) xs[c] = x[(size_t)n * DIMD + c];
        __syncthreads();

        // x2 in fp64
        double p = 0.0;
        for (int c = tid; c < DIMD; c += 256) { double v = xs[c]; p = fma(v, v, p); }
        red[tid] = p; __syncthreads();
        for (int s = 128; s > 0; s >>= 1) {
            if (tid < s) red[tid] += red[tid + s];
            __syncthreads();
        }
        float x2_32 = (float)red[0];

        // all K codes: 16 per thread, 4-way ILP batches, ascending k per thread
        float bd = FLT_MAX; int bi = 0x7fffffff;
        for (int j = 0; j < 16; j += 4) {
            int k0 = tid + (j + 0) * 256;
            int k1 = tid + (j + 1) * 256;
            int k2 = tid + (j + 2) * 256;
            int k3 = tid + (j + 3) * 256;
            const float* p0 = cb + (size_t)k0 * DIMD;
            const float* p1 = cb + (size_t)k1 * DIMD;
            const float* p2 = cb + (size_t)k2 * DIMD;
            const float* p3 = cb + (size_t)k3 * DIMD;
            double a0 = 0, a1 = 0, a2 = 0, a3 = 0;
            for (int d = 0; d < DIMD; d++) {
                double xv = xs[d];
                a0 = fma(xv, (double)p0[d], a0);
                a1 = fma(xv, (double)p1[d], a1);
                a2 = fma(xv, (double)p2[d], a2);
                a3 = fma(xv, (double)p3[d], a3);
            }
            int   ks[4] = {k0, k1, k2, k3};
            double as[4] = {a0, a1, a2, a3};
            #pragma unroll
            for (int q = 0; q < 4; q++) {
                float e32 = (float)as[q];
                float t1  = x2_32 + (float)g_c2d[ks[q]];   // fl(x2 + c2)
                float dd  = fmaf(-2.f, e32, t1);           // fl(t1 - 2*dot)
                if (dd < bd || (dd == bd && ks[q] < bi)) { bd = dd; bi = ks[q]; }
            }
        }
        rb[tid] = bd; ri[tid] = bi; __syncthreads();
        for (int s = 128; s > 0; s >>= 1) {
            if (tid < s) {
                float ov = rb[tid + s]; int oi = ri[tid + s];
                if (ov < rb[tid] || (ov == rb[tid] && oi < ri[tid])) {
                    rb[tid] = ov; ri[tid] = oi;
                }
            }
            __syncthreads();
        }
        int win = ri[0];

        for (int c = tid; c < DIMD; c += 256) {
            float xv = xs[c];
            float q = cb[(size_t)win * DIMD + c];
            out[(size_t)n * DIMD + c] = xv + (q - xv);
        }
        if (tid == 0 && out_size >= (long long)N * DIMD + N)
            out[(long long)N * DIMD + n] = (float)win;
        __syncthreads();
    }
}

extern "C" void kernel_launch(void* const* d_in, const int* in_sizes, int n_in,
                              void* d_out, int out_size) {
    const float* x  = (const float*)d_in[0];
    const float* cb = (const float*)d_in[1];
    const int N = in_sizes[0] / DIMD;
    const int K = in_sizes[1] / DIMD;

    float* d_x2;   cudaGetSymbolAddress((void**)&d_x2, g_x2);
    int*   d_nf;   cudaGetSymbolAddress((void**)&d_nf, g_nflag);

    cudaMemsetAsync(d_nf, 0, sizeof(int));
    c2d_kernel<<<16, 256>>>(cb, K);
    sqnorm_kernel<<<128, 256>>>(x, d_x2, N);
    vq_kernel<<<N / TM, 256>>>(x, cb, (float*)d_out, N, K, (long long)out_size);
    rescore_kernel<<<128, 256>>>(x, cb, (float*)d_out, N, K, (long long)out_size);

    long long need = (long long)N * DIMD + N;
    if ((long long)out_size > need) {
        cudaMemsetAsync((float*)d_out + need, 0,
                        ((long long)out_size - need) * sizeof(float));
    }
}

// round 5
// speedup vs baseline: 3.9990x; 3.9990x over previous
#include <cuda_runtime.h>
#include <cuda_bf16.h>
#include <cfloat>
#include <cstdint>

// PromptVQ: x[65536,768] f32, codebook[4096,768] f32 -> q_ste[65536,768] f32 + indices tail.
// Phase 1: bf16 HMMA (mma.sync) GEMM of hi parts; per-token running min; flag candidates
//          with approx dist < min + 1.5 (6 sigma of bf16 truncation noise) to a pair list.
// Phase 2: exact rescore of pairs (fp64 dot + reference fp32 cascade), first-index ties.
// Phase 3: gather winners -> STE output + index tail.

#define DIMD   768
#define NTOK   65536
#define KCODE  4096
#define TM     128
#define NTILE  128
#define NTILES (KCODE / NTILE)   // 32
#define KC     32                // dims per k-chunk
#define NKC    (DIMD / KC)       // 24
#define MARGIN 1.5f
#define PAIR_CAP (4 << 20)

// ---- device globals ----
__device__ __nv_bfloat16 g_xhi[(size_t)NTOK * DIMD];
__device__ __nv_bfloat16 g_chi[(size_t)KCODE * DIMD];
__device__ double g_x2d[NTOK];
__device__ double g_c2d[KCODE];
__device__ float  g_c2f[KCODE];
__device__ unsigned long long g_best[NTOK];
__device__ unsigned int g_pairs[PAIR_CAP];
__device__ int g_npair;

// ---- helpers ----
static __device__ __forceinline__ uint32_t smem_u32(const void* p) {
    uint32_t a;
    asm("{ .reg .u64 t; cvta.to.shared.u64 t, %1; cvt.u32.u64 %0, t; }" : "=r"(a) : "l"(p));
    return a;
}
static __device__ __forceinline__ uint32_t fkey(float f) {   // monotone float->uint
    uint32_t u = __float_as_uint(f);
    return u ^ ((uint32_t)((int)u >> 31) | 0x80000000u);
}
static __device__ __forceinline__ float unkey(uint32_t k) {
    uint32_t u = k ^ (((int)k >= 0) ? 0xFFFFFFFFu : 0x80000000u);
    return __uint_as_float(u);
}
static __device__ __forceinline__ void ldsm4(uint32_t* r, uint32_t addr) {
    asm volatile("ldmatrix.sync.aligned.m8n8.x4.shared.b16 {%0,%1,%2,%3}, [%4];"
                 : "=r"(r[0]), "=r"(r[1]), "=r"(r[2]), "=r"(r[3]) : "r"(addr));
}
static __device__ __forceinline__ void mma16816(float* d, const uint32_t* a, const uint32_t* b) {
    asm volatile("mma.sync.aligned.m16n8k16.row.col.f32.bf16.bf16.f32 "
                 "{%0,%1,%2,%3}, {%4,%5,%6,%7}, {%8,%9}, {%0,%1,%2,%3};"
                 : "+f"(d[0]), "+f"(d[1]), "+f"(d[2]), "+f"(d[3])
                 : "r"(a[0]), "r"(a[1]), "r"(a[2]), "r"(a[3]), "r"(b[0]), "r"(b[1]));
}

// ---- prologue: bf16 hi conversion + fp64 norms ----
__global__ void xprep_kernel(const float* __restrict__ x, int rows) {
    int w = (blockIdx.x * blockDim.x + threadIdx.x) >> 5;
    int lane = threadIdx.x & 31;
    int nw = (gridDim.x * blockDim.x) >> 5;
    for (int r = w; r < rows; r += nw) {
        const float* p = x + (size_t)r * DIMD;
        __nv_bfloat16* h = g_xhi + (size_t)r * DIMD;
        double s = 0.0;
        for (int c = lane * 4; c < DIMD; c += 128) {
            float4 v = *(const float4*)(p + c);
            s = fma((double)v.x, (double)v.x, s);
            s = fma((double)v.y, (double)v.y, s);
            s = fma((double)v.z, (double)v.z, s);
            s = fma((double)v.w, (double)v.w, s);
            __nv_bfloat162 h0 = __floats2bfloat162_rn(v.x, v.y);
            __nv_bfloat162 h1 = __floats2bfloat162_rn(v.z, v.w);
            uint2 st;
            st.x = *(uint32_t*)&h0;
            st.y = *(uint32_t*)&h1;
            *(uint2*)(h + c) = st;
        }
        #pragma unroll
        for (int o = 16; o > 0; o >>= 1) s += __shfl_xor_sync(0xffffffffu, s, o);
        if (lane == 0) g_x2d[r] = s;
    }
}

__global__ void cprep_kernel(const float* __restrict__ cb, int rows) {
    int w = (blockIdx.x * blockDim.x + threadIdx.x) >> 5;
    int lane = threadIdx.x & 31;
    int nw = (gridDim.x * blockDim.x) >> 5;
    for (int r = w; r < rows; r += nw) {
        const float* p = cb + (size_t)r * DIMD;
        __nv_bfloat16* h = g_chi + (size_t)r * DIMD;
        double s = 0.0;
        for (int c = lane * 4; c < DIMD; c += 128) {
            float4 v = *(const float4*)(p + c);
            s = fma((double)v.x, (double)v.x, s);
            s = fma((double)v.y, (double)v.y, s);
            s = fma((double)v.z, (double)v.z, s);
            s = fma((double)v.w, (double)v.w, s);
            __nv_bfloat162 h0 = __floats2bfloat162_rn(v.x, v.y);
            __nv_bfloat162 h1 = __floats2bfloat162_rn(v.z, v.w);
            uint2 st;
            st.x = *(uint32_t*)&h0;
            st.y = *(uint32_t*)&h1;
            *(uint2*)(h + c) = st;
        }
        #pragma unroll
        for (int o = 16; o > 0; o >>= 1) s += __shfl_xor_sync(0xffffffffu, s, o);
        if (lane == 0) { g_c2d[r] = s; g_c2f[r] = (float)s; }
    }
}

// ---- SMEM layout (dynamic): A panel | B ring | c2 cache | per-token min ----
#define A_OFF   0
#define B_OFF   196608
#define C2_OFF  212992
#define MIN_OFF 229376
#define SMEM_TOTAL 229888

__global__ __launch_bounds__(256, 1)
void vq_mma_kernel(const float* __restrict__ x, const float* __restrict__ cb) {
    extern __shared__ char sm[];
    const uint32_t sb = smem_u32(sm);
    const int tid = threadIdx.x, wid = tid >> 5, lane = tid & 31;
    const int wm = wid & 3, wn = wid >> 2;
    const int m0 = blockIdx.x * TM;

    uint32_t* sMin = (uint32_t*)(sm + MIN_OFF);
    float*    c2s  = (float*)(sm + C2_OFF);
    if (tid < TM) sMin[tid] = 0xFFFFFFFFu;
    for (int i = tid; i < KCODE; i += 256) c2s[i] = g_c2f[i];

    // A panel: 128 rows x 768 bf16, grouped per k16: addr = g*4096 + (m*2+h)*16
    #pragma unroll 4
    for (int it = 0; it < 48; it++) {
        int v = it * 256 + tid;
        int m = v / 96, c = v % 96, g = c >> 1, h = c & 1;
        uint4 d = *(const uint4*)(g_xhi + (size_t)(m0 + m) * DIMD + g * 16 + h * 8);
        *(uint4*)(sm + A_OFF + g * 4096 + (m * 2 + h) * 16) = d;
    }
    __syncthreads();

    for (int nt = 0; nt < NTILES; nt++) {
        float acc[2][8][4];
        #pragma unroll
        for (int a = 0; a < 2; a++)
            #pragma unroll
            for (int b = 0; b < 8; b++)
                #pragma unroll
                for (int q = 0; q < 4; q++) acc[a][b][q] = 0.f;

        // prefetch chunk 0: each thread 2x16B (units w = 2*tid, 2*tid+1)
        const int pn = tid >> 1;                 // code row within tile
        const int pgg = tid & 1;                 // k16 group within chunk
        uint4 pf0, pf1;
        {
            const __nv_bfloat16* src = g_chi + (size_t)(nt * NTILE + pn) * DIMD + 0 * KC + pgg * 16;
            pf0 = *(const uint4*)(src);
            pf1 = *(const uint4*)(src + 8);
        }
        int s = 0;
        for (int kc = 0; kc < NKC; kc++) {
            // store prefetched chunk into buffer s
            *(uint4*)(sm + B_OFF + s * 8192 + pgg * 4096 + (pn * 2 + 0) * 16) = pf0;
            *(uint4*)(sm + B_OFF + s * 8192 + pgg * 4096 + (pn * 2 + 1) * 16) = pf1;
            __syncthreads();
            if (kc + 1 < NKC) {
                const __nv_bfloat16* src = g_chi + (size_t)(nt * NTILE + pn) * DIMD + (kc + 1) * KC + pgg * 16;
                pf0 = *(const uint4*)(src);
                pf1 = *(const uint4*)(src + 8);
            }
            // compute: 2 k16 groups in this chunk
            #pragma unroll
            for (int gg = 0; gg < 2; gg++) {
                const int ga = kc * 2 + gg;
                uint32_t af[2][4];
                #pragma unroll
                for (int mf = 0; mf < 2; mf++) {
                    int mrow = wm * 32 + mf * 16 + (lane & 15);
                    uint32_t u = mrow * 2 + (lane >> 4);
                    ldsm4(af[mf], sb + A_OFF + ga * 4096 + u * 16);
                }
                #pragma unroll
                for (int fq = 0; fq < 4; fq++) {
                    int n = wn * 64 + fq * 16 + ((lane & 7) | ((lane & 16) >> 1));
                    uint32_t u = n * 2 + ((lane >> 3) & 1);
                    uint32_t bf[4];
                    ldsm4(bf, sb + B_OFF + s * 8192 + gg * 4096 + u * 16);
                    #pragma unroll
                    for (int mf = 0; mf < 2; mf++) {
                        mma16816(acc[mf][fq * 2],     af[mf], bf);
                        mma16816(acc[mf][fq * 2 + 1], af[mf], bf + 2);
                    }
                }
            }
            s ^= 1;
        }

        // ---- epilogue: running-min update ----
        float rmin[2][2] = {{FLT_MAX, FLT_MAX}, {FLT_MAX, FLT_MAX}};
        #pragma unroll
        for (int mf = 0; mf < 2; mf++)
            #pragma unroll
            for (int nf = 0; nf < 8; nf++) {
                int cl = wn * 64 + nf * 8 + 2 * (lane & 3);
                float c2a = c2s[nt * NTILE + cl];
                float c2b = c2s[nt * NTILE + cl + 1];
                float d0 = fmaf(-2.f, acc[mf][nf][0], c2a);
                float d1 = fmaf(-2.f, acc[mf][nf][1], c2b);
                float d2 = fmaf(-2.f, acc[mf][nf][2], c2a);
                float d3 = fmaf(-2.f, acc[mf][nf][3], c2b);
                rmin[mf][0] = fminf(rmin[mf][0], fminf(d0, d1));
                rmin[mf][1] = fminf(rmin[mf][1], fminf(d2, d3));
            }
        #pragma unroll
        for (int o = 1; o <= 2; o <<= 1) {
            #pragma unroll
            for (int mf = 0; mf < 2; mf++) {
                rmin[mf][0] = fminf(rmin[mf][0], __shfl_xor_sync(0xffffffffu, rmin[mf][0], o));
                rmin[mf][1] = fminf(rmin[mf][1], __shfl_xor_sync(0xffffffffu, rmin[mf][1], o));
            }
        }
        if ((lane & 3) == 0) {
            #pragma unroll
            for (int mf = 0; mf < 2; mf++) {
                int mlo = wm * 32 + mf * 16 + (lane >> 2);
                atomicMin(&sMin[mlo],     fkey(rmin[mf][0]));
                atomicMin(&sMin[mlo + 8], fkey(rmin[mf][1]));
            }
        }
        __syncthreads();

        // ---- flag pass: emit candidates within margin of running min ----
        #pragma unroll
        for (int mf = 0; mf < 2; mf++) {
            int mlo = wm * 32 + mf * 16 + (lane >> 2);
            float tlo = unkey(sMin[mlo]) + MARGIN;
            float thi = unkey(sMin[mlo + 8]) + MARGIN;
            int toklo = m0 + mlo, tokhi = toklo + 8;
            #pragma unroll
            for (int nf = 0; nf < 8; nf++) {
                int cl = wn * 64 + nf * 8 + 2 * (lane & 3);
                int kg = nt * NTILE + cl;
                float c2a = c2s[kg], c2b = c2s[kg + 1];
                float d0 = fmaf(-2.f, acc[mf][nf][0], c2a);
                float d1 = fmaf(-2.f, acc[mf][nf][1], c2b);
                float d2 = fmaf(-2.f, acc[mf][nf][2], c2a);
                float d3 = fmaf(-2.f, acc[mf][nf][3], c2b);
                if (d0 < tlo) { int sl = atomicAdd(&g_npair, 1); if (sl < PAIR_CAP) g_pairs[sl] = ((unsigned)toklo << 12) | (unsigned)kg; }
                if (d1 < tlo) { int sl = atomicAdd(&g_npair, 1); if (sl < PAIR_CAP) g_pairs[sl] = ((unsigned)toklo << 12) | (unsigned)(kg + 1); }
                if (d2 < thi) { int sl = atomicAdd(&g_npair, 1); if (sl < PAIR_CAP) g_pairs[sl] = ((unsigned)tokhi << 12) | (unsigned)kg; }
                if (d3 < thi) { int sl = atomicAdd(&g_npair, 1); if (sl < PAIR_CAP) g_pairs[sl] = ((unsigned)tokhi << 12) | (unsigned)(kg + 1); }
            }
        }
        __syncthreads();
    }
}

// ---- exact rescore: fp64 dot + reference fp32 cascade; atomicMin on (distkey, k) ----
__global__ void rescore_kernel(const float* __restrict__ x, const float* __restrict__ cb) {
    int np = g_npair; if (np > PAIR_CAP) np = PAIR_CAP;
    int w = (blockIdx.x * blockDim.x + threadIdx.x) >> 5;
    int lane = threadIdx.x & 31;
    int nw = (gridDim.x * blockDim.x) >> 5;
    for (int i = w; i < np; i += nw) {
        unsigned pr = g_pairs[i];
        int n = pr >> 12, k = pr & 4095;
        const float* xp = x + (size_t)n * DIMD;
        const float* cp = cb + (size_t)k * DIMD;
        double s = 0.0;
        for (int c = lane; c < DIMD; c += 32) s = fma((double)xp[c], (double)cp[c], s);
        #pragma unroll
        for (int o = 16; o > 0; o >>= 1) s += __shfl_xor_sync(0xffffffffu, s, o);
        if (lane == 0) {
            float t1 = (float)g_x2d[n] + (float)g_c2d[k];     // fl(x2 + c2)
            float dd = fmaf(-2.f, (float)s, t1);              // fl(t1 - 2*dot)
            unsigned long long key = ((unsigned long long)fkey(dd) << 32) | (unsigned)k;
            atomicMin(&g_best[n], key);
        }
    }
}

// ---- gather winners -> STE output + index tail ----
__global__ void output_kernel(const float* __restrict__ x, const float* __restrict__ cb,
                              float* __restrict__ out, long long out_size) {
    int w = (blockIdx.x * blockDim.x + threadIdx.x) >> 5;
    int lane = threadIdx.x & 31;
    if (w >= NTOK) return;
    int k = (int)(g_best[w] & 0xFFFFFFFFull);
    const float4* xp = (const float4*)(x + (size_t)w * DIMD);
    const float4* cp = (const float4*)(cb + (size_t)k * DIMD);
    float4* op = (float4*)(out + (size_t)w * DIMD);
    #pragma unroll
    for (int c = lane; c < DIMD / 4; c += 32) {
        float4 xv = xp[c], qv = cp[c], o;
        o.x = xv.x + (qv.x - xv.x);
        o.y = xv.y + (qv.y - xv.y);
        o.z = xv.z + (qv.z - xv.z);
        o.w = xv.w + (qv.w - xv.w);
        op[c] = o;
    }
    long long ND = (long long)NTOK * DIMD;
    if (lane == 0 && out_size >= ND + NTOK) out[ND + w] = (float)k;
}

// ---- launcher ----
extern "C" void kernel_launch(void* const* d_in, const int* in_sizes, int n_in,
                              void* d_out, int out_size) {
    const float* x  = (const float*)d_in[0];
    const float* cb = (const float*)d_in[1];

    void *d_best, *d_np;
    cudaGetSymbolAddress(&d_best, g_best);
    cudaGetSymbolAddress(&d_np, g_npair);

    static int smem_set = 0;
    if (!smem_set) {
        cudaFuncSetAttribute(vq_mma_kernel, cudaFuncAttributeMaxDynamicSharedMemorySize, SMEM_TOTAL);
        smem_set = 1;
    }

    cudaMemsetAsync(d_best, 0xFF, (size_t)NTOK * 8);
    cudaMemsetAsync(d_np, 0, sizeof(int));
    xprep_kernel<<<512, 256>>>(x, NTOK);
    cprep_kernel<<<64, 256>>>(cb, KCODE);
    vq_mma_kernel<<<NTOK / TM, 256, SMEM_TOTAL>>>(x, cb);
    rescore_kernel<<<2048, 256>>>(x, cb);
    output_kernel<<<NTOK / 8, 256>>>(x, cb, (float*)d_out, (long long)out_size);

    long long need = (long long)NTOK * DIMD + NTOK;
    if ((long long)out_size > need) {
        cudaMemsetAsync((float*)d_out + need, 0,
                        ((long long)out_size - need) * sizeof(float));
    }
}